// round 3
// baseline (speedup 1.0000x reference)
#include <cuda_runtime.h>
#include <cuda_bf16.h>
#include <math.h>

#define BB 64
#define TT 2048
#define DIM 256
#define VOCAB 32000
#define EPS_CUT 1e-9f

// Scratch (static __device__ globals: no allocation)
__device__ float d_w[BB * TT];              // per-step weight (1-g)*suffixprod (tail only)
__device__ int   d_t0[BB];                  // cutoff index per batch
// hT split into bf16 hi/lo, stored K-INTERLEAVED: within each 8-word (16-dim)
// group, original word j (pair of dims 2j,2j+1) sits at ((j&3)<<1)|(j>>2),
// so k_head's A fragments (words tig and tig+4) are one aligned LDG.64.
__device__ __nv_bfloat16 d_hThi[BB * DIM];
__device__ __nv_bfloat16 d_hTlo[BB * DIM];

// ---------------------------------------------------------------------------
// K1: fused tail gate scan. One block per b, 256 threads.
// Processes 32-token chunks from the END of the sequence: 8 threads per token
// compute z = emb[x[b,t]].Wg, leaders apply sigmoid, thread 0 runs the serial
// suffix product, writing w_t = (1-g_t)*S_t and stopping once S < EPS_CUT.
// Only ~2 chunks typically run -> no full-vocab / full-T gate pass needed.
// ---------------------------------------------------------------------------
__global__ void k_scan(const int* __restrict__ x, const float* __restrict__ emb,
                       const float* __restrict__ Wg, const float* __restrict__ Wg_b) {
    int b = blockIdx.x, tid = threadIdx.x;
    int tok = tid >> 3, sub = tid & 7;
    __shared__ float g_sh[32];
    __shared__ int s_t0;
    if (tid == 0) s_t0 = -1;
    __syncthreads();
    float gb = Wg_b[0];
    float S = 1.f;  // only thread 0's copy is used

    const float4* w4 = (const float4*)Wg;
    float4 wv[8];
#pragma unroll
    for (int i = 0; i < 8; i++) wv[i] = w4[sub * 8 + i];

    for (int chunk = 0; chunk < TT / 32; chunk++) {
        int tbase = TT - 32 * (chunk + 1);
        int t = tbase + tok;
        int xv = x[b * TT + t];
        const float4* e4 = (const float4*)(emb + (size_t)xv * DIM);
        float z = 0.f;
#pragma unroll
        for (int i = 0; i < 8; i++) {
            float4 e = e4[sub * 8 + i];
            z += e.x * wv[i].x + e.y * wv[i].y + e.z * wv[i].z + e.w * wv[i].w;
        }
        z += __shfl_xor_sync(0xffffffffu, z, 1);
        z += __shfl_xor_sync(0xffffffffu, z, 2);
        z += __shfl_xor_sync(0xffffffffu, z, 4);
        if (sub == 0) g_sh[tok] = 1.f / (1.f + expf(-(z + gb)));
        __syncthreads();
        if (tid == 0) {
            for (int j = 31; j >= 0; j--) {
                float gg = g_sh[j];
                d_w[b * TT + tbase + j] = (1.f - gg) * S;
                S *= gg;
                if (S < EPS_CUT) { s_t0 = tbase + j; break; }
            }
            if (tbase == 0 && s_t0 < 0) s_t0 = 0;
        }
        __syncthreads();
        if (s_t0 >= 0) break;
    }
    if (tid == 0) d_t0[b] = s_t0;
}

// ---------------------------------------------------------------------------
// K2: hT[b,:] = sum_{t>=t0} w_t * tanh(W @ emb[x[b,t]] + Wb)
// Grid (2 d-halves, 64 b), 512 threads. One block exclusively owns its 128 d.
//   thread: warp w, lane l; d = w*8 + (l>>2); kq = l&3 (64-elem k quarter)
//   W quarter in registers; k-reduction via 2 shuffles (no smem partials);
//   e row double-buffered in smem, ONE barrier per timestep.
// Writes the bf16 hi/lo split directly (no atomics, no extra kernel).
// ---------------------------------------------------------------------------
__global__ void __launch_bounds__(512, 1) k_main(
        const int* __restrict__ x, const float* __restrict__ emb,
        const float* __restrict__ W, const float* __restrict__ Wb) {
    int dh = blockIdx.x;
    int b = blockIdx.y;
    int tid = threadIdx.x;
    int lane = tid & 31, w = tid >> 5;
    int kq = lane & 3;
    int dg = dh * 128 + w * 8 + (lane >> 2);

    float wreg[64];
    const float4* W4 = (const float4*)(W + (size_t)dg * DIM + kq * 64);
#pragma unroll
    for (int i = 0; i < 16; i++) {
        float4 v = W4[i];
        wreg[4 * i + 0] = v.x; wreg[4 * i + 1] = v.y;
        wreg[4 * i + 2] = v.z; wreg[4 * i + 3] = v.w;
    }
    float wb = Wb[dg];
    int t0 = d_t0[b];

    __shared__ float e_s[2][DIM];
    float acc = 0.f;
    int cur = 0;
    if (tid < DIM) {
        int xv = x[b * TT + TT - 1];
        e_s[0][tid] = emb[(size_t)xv * DIM + tid];
    }
    __syncthreads();

    for (int t = TT - 1; t >= t0; t--) {
        int tn = t - 1;
        if (tn >= t0 && tid < DIM) {   // prefetch into other buffer (no hazard)
            int xv = x[b * TT + tn];
            e_s[cur ^ 1][tid] = emb[(size_t)xv * DIM + tid];
        }
        const float4* ev = (const float4*)&e_s[cur][kq * 64];
        float s0 = 0.f, s1 = 0.f, s2 = 0.f, s3 = 0.f;
#pragma unroll
        for (int i = 0; i < 16; i++) {
            float4 e = ev[i];
            s0 = fmaf(wreg[4 * i + 0], e.x, s0);
            s1 = fmaf(wreg[4 * i + 1], e.y, s1);
            s2 = fmaf(wreg[4 * i + 2], e.z, s2);
            s3 = fmaf(wreg[4 * i + 3], e.w, s3);
        }
        float ps = (s0 + s1) + (s2 + s3);
        ps += __shfl_xor_sync(0xffffffffu, ps, 1);
        ps += __shfl_xor_sync(0xffffffffu, ps, 2);
        float wt = d_w[b * TT + t];
        acc = fmaf(wt, tanhf(ps + wb), acc);
        __syncthreads();
        cur ^= 1;
    }

    if ((lane & 3) == 0) {
        __nv_bfloat16 hi = __float2bfloat16_rn(acc);
        __nv_bfloat16 lo = __float2bfloat16_rn(acc - __bfloat162float(hi));
        int jdg = dg >> 1;
        int g8 = jdg >> 3, jin = jdg & 7;
        int j2 = ((jin & 3) << 1) | (jin >> 2);           // interleave for LDG.64
        int pos = b * DIM + (g8 * 8 + j2) * 2 + (dg & 1);
        d_hThi[pos] = hi;
        d_hTlo[pos] = lo;
    }
}

// ---------------------------------------------------------------------------
// K3: out = hT @ head_w^T + head_b via bf16-split mma.sync.
//   out = Ahi*Bhi + Ahi*Blo + Alo*Bhi (fp32 accum; lo*lo dropped ~2^-16)
// ZERO shared memory, ZERO barriers: B (head_w fp32) loads land exactly on
// fragment layout as float2 -> split to bf16 in registers; A fragments are
// LDG.64 from the interleaved hi/lo arrays (L1-resident, 64KB).
// 125 blocks x 256 thr; block tile M=64(all b) x N=256 v; warp tile 64x32.
// ---------------------------------------------------------------------------
__device__ __forceinline__ void mma_bf16(float* d, const unsigned* a,
                                         const unsigned* b) {
    asm volatile(
        "mma.sync.aligned.m16n8k16.row.col.f32.bf16.bf16.f32 "
        "{%0,%1,%2,%3},{%4,%5,%6,%7},{%8,%9},{%0,%1,%2,%3};\n"
        : "+f"(d[0]), "+f"(d[1]), "+f"(d[2]), "+f"(d[3])
        : "r"(a[0]), "r"(a[1]), "r"(a[2]), "r"(a[3]), "r"(b[0]), "r"(b[1]));
}

__global__ void __launch_bounds__(256, 1) k_head_tc(
        const float* __restrict__ hw, const float* __restrict__ hb,
        float* __restrict__ out) {
    int tid = threadIdx.x;
    int w = tid >> 5, lane = tid & 31;
    int g = lane >> 2, tig = lane & 3;
    int vbase = blockIdx.x * 256;

    float acc[4][4][4];
#pragma unroll
    for (int mt = 0; mt < 4; mt++)
#pragma unroll
        for (int nt = 0; nt < 4; nt++)
#pragma unroll
            for (int r = 0; r < 4; r++) acc[mt][nt][r] = 0.f;

    const uint2* Ah2 = (const uint2*)d_hThi;   // [64][64] uint2 (interleaved)
    const uint2* Al2 = (const uint2*)d_hTlo;

    for (int kc = 0; kc < 16; kc++) {
        // ---- B fragments: straight from global fp32, split in registers ----
        unsigned bh[4][2], bl[4][2];
#pragma unroll
        for (int nt = 0; nt < 4; nt++) {
            int v = vbase + w * 32 + nt * 8 + g;
            const float* r = hw + (size_t)v * DIM + kc * 16 + 2 * tig;
            float2 f0 = *(const float2*)r;
            float2 f1 = *(const float2*)(r + 8);
            __nv_bfloat162 h0 = __float22bfloat162_rn(f0);
            float2 r0 = make_float2(f0.x - __bfloat162float(h0.x),
                                    f0.y - __bfloat162float(h0.y));
            __nv_bfloat162 l0 = __float22bfloat162_rn(r0);
            __nv_bfloat162 h1 = __float22bfloat162_rn(f1);
            float2 r1 = make_float2(f1.x - __bfloat162float(h1.x),
                                    f1.y - __bfloat162float(h1.y));
            __nv_bfloat162 l1 = __float22bfloat162_rn(r1);
            bh[nt][0] = *(unsigned*)&h0; bh[nt][1] = *(unsigned*)&h1;
            bl[nt][0] = *(unsigned*)&l0; bl[nt][1] = *(unsigned*)&l1;
        }
        // ---- A fragments: LDG.64 from interleaved hi/lo (L1-resident) ----
        unsigned ahi[4][4], alo[4][4];
#pragma unroll
        for (int mt = 0; mt < 4; mt++) {
            int m0 = mt * 16 + g;
            uint2 a0 = Ah2[m0 * 64 + kc * 4 + tig];
            uint2 a1 = Ah2[(m0 + 8) * 64 + kc * 4 + tig];
            ahi[mt][0] = a0.x; ahi[mt][1] = a1.x;
            ahi[mt][2] = a0.y; ahi[mt][3] = a1.y;
            uint2 c0 = Al2[m0 * 64 + kc * 4 + tig];
            uint2 c1 = Al2[(m0 + 8) * 64 + kc * 4 + tig];
            alo[mt][0] = c0.x; alo[mt][1] = c1.x;
            alo[mt][2] = c0.y; alo[mt][3] = c1.y;
        }
#pragma unroll
        for (int nt = 0; nt < 4; nt++)
#pragma unroll
            for (int mt = 0; mt < 4; mt++) {
                mma_bf16(acc[mt][nt], ahi[mt], bh[nt]);
                mma_bf16(acc[mt][nt], ahi[mt], bl[nt]);
                mma_bf16(acc[mt][nt], alo[mt], bh[nt]);
            }
    }

    // epilogue: add bias, write out [b, VOCAB]
#pragma unroll
    for (int nt = 0; nt < 4; nt++) {
        int v = vbase + w * 32 + nt * 8 + tig * 2;
        float2 bias = *(const float2*)&hb[v];
#pragma unroll
        for (int mt = 0; mt < 4; mt++) {
            int b0r = mt * 16 + g;
            float2 o0, o1;
            o0.x = acc[mt][nt][0] + bias.x;
            o0.y = acc[mt][nt][1] + bias.y;
            o1.x = acc[mt][nt][2] + bias.x;
            o1.y = acc[mt][nt][3] + bias.y;
            *(float2*)&out[(size_t)b0r * VOCAB + v] = o0;
            *(float2*)&out[(size_t)(b0r + 8) * VOCAB + v] = o1;
        }
    }
}

// ---------------------------------------------------------------------------
extern "C" void kernel_launch(void* const* d_in, const int* in_sizes, int n_in,
                              void* d_out, int out_size) {
    const int*   x      = (const int*)d_in[0];
    const float* emb    = (const float*)d_in[1];
    const float* W_w    = (const float*)d_in[2];
    const float* W_b    = (const float*)d_in[3];
    const float* Wg_w   = (const float*)d_in[4];
    const float* Wg_b   = (const float*)d_in[5];
    const float* head_w = (const float*)d_in[6];
    const float* head_b = (const float*)d_in[7];
    float* out = (float*)d_out;

    k_scan<<<BB, 256>>>(x, emb, Wg_w, Wg_b);
    k_main<<<dim3(2, BB), 512>>>(x, emb, W_w, W_b);
    k_head_tc<<<VOCAB / 256, 256>>>(head_w, head_b, out);
}